// round 15
// baseline (speedup 1.0000x reference)
#include <cuda_runtime.h>
#include <cuda_bf16.h>
#include <float.h>

#define N_NODES 100000
#define N_EDGES 1600000
#define EQ      (N_EDGES / 4)        // 400000
#define FDIM    32
#define NEG_SLOPE 0.2f

// ---------------- scratch (static device globals; no allocation) ------------
__device__ __align__(16) float g_xl [N_NODES * FDIM];   // source transform
__device__ __align__(16) float g_xr [N_NODES * FDIM];   // target transform
__device__ __align__(16) float g_h  [N_NODES * FDIM];   // layer-1 output (relu'd)
__device__ __align__(16) float g_acc[N_NODES * FDIM];   // unnormalized aggregation
                                                        // invariant: zero between launches
__device__ float g_z1  [N_NODES];         // sum of exp(score), layer 1
__device__ float g_z2  [N_NODES];         // sum of exp(score), layer 2
__device__ float g_cnt [N_NODES];         // in-degree (float, matches ref)
__device__ float g_suma[N_NODES];         // sum of edge_attr per target

// ---------------- kernels ---------------------------------------------------

// per-launch reset of the small node state only. g_acc stays zero by the
// k_fin invariant (read+reset by the same thread), so no 12.8MB pass here.
__global__ void k_init() {
    int i = blockIdx.x * blockDim.x + threadIdx.x;
    if (i < N_NODES) { g_z1[i] = 0.0f; g_z2[i] = 0.0f; g_cnt[i] = 0.0f; g_suma[i] = 0.0f; }
}

__global__ void k_stats(const int* __restrict__ dst, const float* __restrict__ ea) {
    int e = blockIdx.x * blockDim.x + threadIdx.x;
    if (e < N_EDGES) {
        int d = dst[e];
        atomicAdd(&g_cnt[d], 1.0f);
        atomicAdd(&g_suma[d], ea[e]);
    }
}

// X[rows,K] @ Wl/Wr[K,32] + bias -> g_xl/g_xr.  (R9 known-good version)
template <int K>
__global__ void __launch_bounds__(256) k_gemm(
        const float4* __restrict__ Xin,
        const float* __restrict__ Wl, const float* __restrict__ bl,
        const float* __restrict__ Wr, const float* __restrict__ br) {
    __shared__ float4 sx[64 * (K / 4)];              // 32KB (K=128) / 8KB (K=32)
    const float4* X4 = Xin ? Xin : (const float4*)g_h;

    int tid  = threadIdx.x;
    int base = blockIdx.x * 64;
    for (int i = tid; i < 64 * (K / 4); i += 256) {
        int row = base + i / (K / 4);
        int kk  = i % (K / 4);
        if (row >= N_NODES) row = N_NODES - 1;       // clamp (stores guarded)
        sx[i] = X4[(long)row * (K / 4) + kk];
    }
    __syncthreads();

    int col = tid & 31;
    int ty  = tid >> 5;

    float al[8], ar[8];
    #pragma unroll
    for (int r = 0; r < 8; r++) { al[r] = 0.f; ar[r] = 0.f; }

    #pragma unroll 4
    for (int k4 = 0; k4 < K / 4; k4++) {
        float wl0 = __ldg(&Wl[(k4 * 4 + 0) * 32 + col]);
        float wl1 = __ldg(&Wl[(k4 * 4 + 1) * 32 + col]);
        float wl2 = __ldg(&Wl[(k4 * 4 + 2) * 32 + col]);
        float wl3 = __ldg(&Wl[(k4 * 4 + 3) * 32 + col]);
        float wr0 = __ldg(&Wr[(k4 * 4 + 0) * 32 + col]);
        float wr1 = __ldg(&Wr[(k4 * 4 + 1) * 32 + col]);
        float wr2 = __ldg(&Wr[(k4 * 4 + 2) * 32 + col]);
        float wr3 = __ldg(&Wr[(k4 * 4 + 3) * 32 + col]);
        #pragma unroll
        for (int r = 0; r < 8; r++) {
            float4 xv = sx[(ty * 8 + r) * (K / 4) + k4];   // warp-uniform bcast
            al[r] = fmaf(xv.x, wl0, al[r]);
            al[r] = fmaf(xv.y, wl1, al[r]);
            al[r] = fmaf(xv.z, wl2, al[r]);
            al[r] = fmaf(xv.w, wl3, al[r]);
            ar[r] = fmaf(xv.x, wr0, ar[r]);
            ar[r] = fmaf(xv.y, wr1, ar[r]);
            ar[r] = fmaf(xv.z, wr2, ar[r]);
            ar[r] = fmaf(xv.w, wr3, ar[r]);
        }
    }
    float bL = bl[col], bR = br[col];
    int row0 = base + ty * 8;
    #pragma unroll
    for (int r = 0; r < 8; r++) {
        int row = row0 + r;
        if (row < N_NODES) {
            g_xl[row * 32 + col] = al[r] + bL;
            g_xr[row * 32 + col] = ar[r] + bR;
        }
    }
}

// Fused edge pass, 4 edges per 8-lane group (stride EQ) for 8 gather chains
// per thread. Random edge order preserved. p = exp(score) (shift-invariant
// softmax), acc[d] += p*xl (red.v4), z[d] += p.
__global__ void __launch_bounds__(256) k_edge(
        const int* __restrict__ src, const int* __restrict__ dst,
        const float* __restrict__ ea,
        const float* __restrict__ We, const float* __restrict__ att,
        int zsel) {
    int g   = blockIdx.x * blockDim.x + threadIdx.x;
    int eb  = g >> 3;
    int sub = g & 7;
    if (eb >= EQ) return;

    int   s[4], d[4];
    float a[4];
    #pragma unroll
    for (int q = 0; q < 4; q++) {
        int e = eb + q * EQ;
        s[q] = src[e]; d[q] = dst[e]; a[q] = ea[e];
    }

    const float4* XL = (const float4*)g_xl;
    const float4* XR = (const float4*)g_xr;
    float4 xl[4], xr[4];
    #pragma unroll
    for (int q = 0; q < 4; q++) xl[q] = __ldg(&XL[s[q] * 8 + sub]);
    #pragma unroll
    for (int q = 0; q < 4; q++) xr[q] = __ldg(&XR[d[q] * 8 + sub]);
    float4 W4 = __ldg(&((const float4*)We)[sub]);
    float4 A4 = __ldg(&((const float4*)att)[sub]);

    float t[4];
    #pragma unroll
    for (int q = 0; q < 4; q++) {
        float v0 = xl[q].x + xr[q].x + a[q] * W4.x;
        float v1 = xl[q].y + xr[q].y + a[q] * W4.y;
        float v2 = xl[q].z + xr[q].z + a[q] * W4.z;
        float v3 = xl[q].w + xr[q].w + a[q] * W4.w;
        v0 = v0 > 0.f ? v0 : NEG_SLOPE * v0;
        v1 = v1 > 0.f ? v1 : NEG_SLOPE * v1;
        v2 = v2 > 0.f ? v2 : NEG_SLOPE * v2;
        v3 = v3 > 0.f ? v3 : NEG_SLOPE * v3;
        t[q] = v0 * A4.x + v1 * A4.y + v2 * A4.z + v3 * A4.w;
    }

    // interleaved independent shuffle reductions
    #pragma unroll
    for (int o = 1; o <= 4; o <<= 1) {
        #pragma unroll
        for (int q = 0; q < 4; q++)
            t[q] += __shfl_xor_sync(0xffffffffu, t[q], o);
    }

    float p[4];
    #pragma unroll
    for (int q = 0; q < 4; q++) p[q] = __expf(t[q]);

    #pragma unroll
    for (int q = 0; q < 4; q++) {
        float* dstp = &g_acc[d[q] * 32 + sub * 4];
        asm volatile("red.global.add.v4.f32 [%0], {%1, %2, %3, %4};"
                     :: "l"(dstp), "f"(p[q] * xl[q].x), "f"(p[q] * xl[q].y),
                        "f"(p[q] * xl[q].z), "f"(p[q] * xl[q].w) : "memory");
    }
    if (sub == 0) {
        float* z = zsel ? g_z2 : g_z1;
        #pragma unroll
        for (int q = 0; q < 4; q++) atomicAdd(&z[d[q]], p[q]);
    }
}

// finalize: add the self-loop contribution (attr = suma/max(cnt,1)), divide,
// add bias; layer1 -> relu into g_h, layer2 -> d_out. Warps are node-aligned
// (block=256): node n = i>>5, lane = feature. Resets g_acc (same-thread).
__global__ void __launch_bounds__(256) k_fin(
        const float* __restrict__ We, const float* __restrict__ att,
        const float* __restrict__ b, float* __restrict__ out,
        int zsel, int do_relu) {
    int i = blockIdx.x * blockDim.x + threadIdx.x;
    if (i >= N_NODES * FDIM) return;
    int n    = i >> 5;
    int lane = i & 31;

    float xl  = g_xl[i];
    float xr  = g_xr[i];
    float acc = g_acc[i];
    float z   = zsel ? g_z2[n] : g_z1[n];
    float mean = g_suma[n] / fmaxf(g_cnt[n], 1.0f);

    float v = xl + xr + mean * __ldg(&We[lane]);
    v = v > 0.f ? v : NEG_SLOPE * v;
    float t = v * __ldg(&att[lane]);
    t += __shfl_xor_sync(0xffffffffu, t, 1);
    t += __shfl_xor_sync(0xffffffffu, t, 2);
    t += __shfl_xor_sync(0xffffffffu, t, 4);
    t += __shfl_xor_sync(0xffffffffu, t, 8);
    t += __shfl_xor_sync(0xffffffffu, t, 16);
    float p = __expf(t);

    float o = (acc + p * xl) / (z + p) + __ldg(&b[lane]);
    if (do_relu) g_h[i] = fmaxf(o, 0.f);
    else         out[i] = o;
    g_acc[i] = 0.0f;                      // restore zero invariant
}

// ---------------- launch ----------------------------------------------------
extern "C" void kernel_launch(void* const* d_in, const int* in_sizes, int n_in,
                              void* d_out, int out_size) {
    const float* x    = (const float*)d_in[0];
    const int*   src  = (const int*)  d_in[1];
    const int*   dst  = (const int*)  d_in[2];
    const float* ea   = (const float*)d_in[3];
    const float* Wl1  = (const float*)d_in[4];
    const float* bl1  = (const float*)d_in[5];
    const float* Wr1  = (const float*)d_in[6];
    const float* br1  = (const float*)d_in[7];
    const float* We1  = (const float*)d_in[8];
    const float* att1 = (const float*)d_in[9];
    const float* b1   = (const float*)d_in[10];
    const float* Wl2  = (const float*)d_in[11];
    const float* bl2  = (const float*)d_in[12];
    const float* Wr2  = (const float*)d_in[13];
    const float* br2  = (const float*)d_in[14];
    const float* We2  = (const float*)d_in[15];
    const float* att2 = (const float*)d_in[16];
    const float* b2   = (const float*)d_in[17];
    float* out = (float*)d_out;

    const int TB   = 256;
    const int NB   = (N_NODES + TB - 1) / TB;
    const int NB32 = (N_NODES * FDIM + TB - 1) / TB;
    const int EB   = (N_EDGES + TB - 1) / TB;
    const int XB   = ((long)EQ * 8 + TB - 1) / TB;      // 4 edges per octet
    const int GB   = (N_NODES + 63) / 64;

    // per-launch node-state reset + degree stats (self-loop attrs)
    k_init<<<NB, TB>>>();
    k_stats<<<EB, TB>>>(dst, ea);

    // ---- layer 1 ----
    k_gemm<128><<<GB, TB>>>((const float4*)x, Wl1, bl1, Wr1, br1);
    k_edge<<<XB, TB>>>(src, dst, ea, We1, att1, 0);
    k_fin<<<NB32, TB>>>(We1, att1, b1, out, 0, 1);

    // ---- layer 2 ----
    k_gemm<32><<<GB, TB>>>(nullptr, Wl2, bl2, Wr2, br2);
    k_edge<<<XB, TB>>>(src, dst, ea, We2, att2, 1);
    k_fin<<<NB32, TB>>>(We2, att2, b2, out, 1, 0);
}

// round 16
// speedup vs baseline: 1.0331x; 1.0331x over previous
#include <cuda_runtime.h>
#include <cuda_bf16.h>
#include <float.h>

#define N_NODES 100000
#define N_EDGES 1600000
#define EHALF   (N_EDGES / 2)        // 800000
#define FDIM    32
#define NEG_SLOPE 0.2f

// ---------------- scratch (static device globals; no allocation) ------------
// INVARIANT: g_acc, g_z1, g_z2, g_cnt, g_suma are all-zero at entry to every
// kernel_launch (BSS-zero initially; k_fin restores zeros each launch).
__device__ __align__(16) float g_xl [N_NODES * FDIM];   // source transform
__device__ __align__(16) float g_xr [N_NODES * FDIM];   // target transform
__device__ __align__(16) float g_h  [N_NODES * FDIM];   // layer-1 output (relu'd)
__device__ __align__(16) float g_acc[N_NODES * FDIM];   // unnormalized aggregation
__device__ float g_z1  [N_NODES];         // sum of exp(score), layer 1
__device__ float g_z2  [N_NODES];         // sum of exp(score), layer 2
__device__ float g_cnt [N_NODES];         // in-degree (float, matches ref)
__device__ float g_suma[N_NODES];         // sum of edge_attr per target

// ---------------- kernels ---------------------------------------------------

// X[rows,K] @ Wl/Wr[K,32] + bias -> g_xl/g_xr.  (R9 known-good version)
template <int K>
__global__ void __launch_bounds__(256) k_gemm(
        const float4* __restrict__ Xin,
        const float* __restrict__ Wl, const float* __restrict__ bl,
        const float* __restrict__ Wr, const float* __restrict__ br) {
    __shared__ float4 sx[64 * (K / 4)];              // 32KB (K=128) / 8KB (K=32)
    const float4* X4 = Xin ? Xin : (const float4*)g_h;

    int tid  = threadIdx.x;
    int base = blockIdx.x * 64;
    for (int i = tid; i < 64 * (K / 4); i += 256) {
        int row = base + i / (K / 4);
        int kk  = i % (K / 4);
        if (row >= N_NODES) row = N_NODES - 1;       // clamp (stores guarded)
        sx[i] = X4[(long)row * (K / 4) + kk];
    }
    __syncthreads();

    int col = tid & 31;
    int ty  = tid >> 5;

    float al[8], ar[8];
    #pragma unroll
    for (int r = 0; r < 8; r++) { al[r] = 0.f; ar[r] = 0.f; }

    #pragma unroll 4
    for (int k4 = 0; k4 < K / 4; k4++) {
        float wl0 = __ldg(&Wl[(k4 * 4 + 0) * 32 + col]);
        float wl1 = __ldg(&Wl[(k4 * 4 + 1) * 32 + col]);
        float wl2 = __ldg(&Wl[(k4 * 4 + 2) * 32 + col]);
        float wl3 = __ldg(&Wl[(k4 * 4 + 3) * 32 + col]);
        float wr0 = __ldg(&Wr[(k4 * 4 + 0) * 32 + col]);
        float wr1 = __ldg(&Wr[(k4 * 4 + 1) * 32 + col]);
        float wr2 = __ldg(&Wr[(k4 * 4 + 2) * 32 + col]);
        float wr3 = __ldg(&Wr[(k4 * 4 + 3) * 32 + col]);
        #pragma unroll
        for (int r = 0; r < 8; r++) {
            float4 xv = sx[(ty * 8 + r) * (K / 4) + k4];   // warp-uniform bcast
            al[r] = fmaf(xv.x, wl0, al[r]);
            al[r] = fmaf(xv.y, wl1, al[r]);
            al[r] = fmaf(xv.z, wl2, al[r]);
            al[r] = fmaf(xv.w, wl3, al[r]);
            ar[r] = fmaf(xv.x, wr0, ar[r]);
            ar[r] = fmaf(xv.y, wr1, ar[r]);
            ar[r] = fmaf(xv.z, wr2, ar[r]);
            ar[r] = fmaf(xv.w, wr3, ar[r]);
        }
    }
    float bL = bl[col], bR = br[col];
    int row0 = base + ty * 8;
    #pragma unroll
    for (int r = 0; r < 8; r++) {
        int row = row0 + r;
        if (row < N_NODES) {
            g_xl[row * 32 + col] = al[r] + bL;
            g_xr[row * 32 + col] = ar[r] + bR;
        }
    }
}

// Fused edge pass, 2 edges per 8-lane group (R14 known-good MLP layout).
// do_stats=1 (layer 1): lanes sub==2/sub==4 also accumulate in-degree and
// edge-attr sums for the self-loop mean (replaces the old k_stats kernel).
__global__ void __launch_bounds__(256) k_edge(
        const int* __restrict__ src, const int* __restrict__ dst,
        const float* __restrict__ ea,
        const float* __restrict__ We, const float* __restrict__ att,
        int zsel, int do_stats) {
    int g   = blockIdx.x * blockDim.x + threadIdx.x;
    int e0  = g >> 3;
    int sub = g & 7;
    if (e0 >= EHALF) return;
    int e1  = e0 + EHALF;

    int s0 = src[e0], d0 = dst[e0];
    int s1 = src[e1], d1 = dst[e1];
    float a0 = ea[e0], a1 = ea[e1];

    // four independent gather chains in flight
    const float4* XL = (const float4*)g_xl;
    const float4* XR = (const float4*)g_xr;
    float4 xl0 = __ldg(&XL[s0 * 8 + sub]);
    float4 xr0 = __ldg(&XR[d0 * 8 + sub]);
    float4 xl1 = __ldg(&XL[s1 * 8 + sub]);
    float4 xr1 = __ldg(&XR[d1 * 8 + sub]);
    float4 W4  = __ldg(&((const float4*)We)[sub]);
    float4 A4  = __ldg(&((const float4*)att)[sub]);

    // degree stats on otherwise-idle lanes (layer 1 only)
    if (do_stats) {
        if (sub == 2) { atomicAdd(&g_cnt[d0], 1.0f); atomicAdd(&g_cnt[d1], 1.0f); }
        if (sub == 4) { atomicAdd(&g_suma[d0], a0);  atomicAdd(&g_suma[d1], a1);  }
    }

    // edge 0 score
    float u0 = xl0.x + xr0.x + a0 * W4.x;
    float u1 = xl0.y + xr0.y + a0 * W4.y;
    float u2 = xl0.z + xr0.z + a0 * W4.z;
    float u3 = xl0.w + xr0.w + a0 * W4.w;
    u0 = u0 > 0.f ? u0 : NEG_SLOPE * u0;
    u1 = u1 > 0.f ? u1 : NEG_SLOPE * u1;
    u2 = u2 > 0.f ? u2 : NEG_SLOPE * u2;
    u3 = u3 > 0.f ? u3 : NEG_SLOPE * u3;
    float t0 = u0 * A4.x + u1 * A4.y + u2 * A4.z + u3 * A4.w;

    // edge 1 score
    float w0 = xl1.x + xr1.x + a1 * W4.x;
    float w1 = xl1.y + xr1.y + a1 * W4.y;
    float w2 = xl1.z + xr1.z + a1 * W4.z;
    float w3 = xl1.w + xr1.w + a1 * W4.w;
    w0 = w0 > 0.f ? w0 : NEG_SLOPE * w0;
    w1 = w1 > 0.f ? w1 : NEG_SLOPE * w1;
    w2 = w2 > 0.f ? w2 : NEG_SLOPE * w2;
    w3 = w3 > 0.f ? w3 : NEG_SLOPE * w3;
    float t1 = w0 * A4.x + w1 * A4.y + w2 * A4.z + w3 * A4.w;

    // interleaved independent shuffle reductions
    t0 += __shfl_xor_sync(0xffffffffu, t0, 1);
    t1 += __shfl_xor_sync(0xffffffffu, t1, 1);
    t0 += __shfl_xor_sync(0xffffffffu, t0, 2);
    t1 += __shfl_xor_sync(0xffffffffu, t1, 2);
    t0 += __shfl_xor_sync(0xffffffffu, t0, 4);
    t1 += __shfl_xor_sync(0xffffffffu, t1, 4);

    float p0 = __expf(t0);
    float p1 = __expf(t1);

    float* dst0 = &g_acc[d0 * 32 + sub * 4];
    asm volatile("red.global.add.v4.f32 [%0], {%1, %2, %3, %4};"
                 :: "l"(dst0), "f"(p0 * xl0.x), "f"(p0 * xl0.y),
                    "f"(p0 * xl0.z), "f"(p0 * xl0.w) : "memory");
    float* dst1 = &g_acc[d1 * 32 + sub * 4];
    asm volatile("red.global.add.v4.f32 [%0], {%1, %2, %3, %4};"
                 :: "l"(dst1), "f"(p1 * xl1.x), "f"(p1 * xl1.y),
                    "f"(p1 * xl1.z), "f"(p1 * xl1.w) : "memory");
    if (sub == 0) {
        float* z = zsel ? g_z2 : g_z1;
        atomicAdd(&z[d0], p0);
        atomicAdd(&z[d1], p1);
    }
}

// finalize: self-loop contribution (attr = suma/max(cnt,1)) + normalize +
// bias; layer1 -> relu into g_h, layer2 -> d_out. Warps are node-aligned:
// node n = i>>5, lane = feature. Resets g_acc (same-thread); layer 2 also
// resets z1/z2/cnt/suma via lane 0 after __syncwarp (same-warp readers).
__global__ void __launch_bounds__(256) k_fin(
        const float* __restrict__ We, const float* __restrict__ att,
        const float* __restrict__ b, float* __restrict__ out,
        int zsel, int do_relu) {
    int i = blockIdx.x * blockDim.x + threadIdx.x;
    if (i >= N_NODES * FDIM) return;
    int n    = i >> 5;
    int lane = i & 31;

    float xl  = g_xl[i];
    float xr  = g_xr[i];
    float acc = g_acc[i];
    float z   = zsel ? g_z2[n] : g_z1[n];
    float mean = g_suma[n] / fmaxf(g_cnt[n], 1.0f);

    float v = xl + xr + mean * __ldg(&We[lane]);
    v = v > 0.f ? v : NEG_SLOPE * v;
    float t = v * __ldg(&att[lane]);
    t += __shfl_xor_sync(0xffffffffu, t, 1);
    t += __shfl_xor_sync(0xffffffffu, t, 2);
    t += __shfl_xor_sync(0xffffffffu, t, 4);
    t += __shfl_xor_sync(0xffffffffu, t, 8);
    t += __shfl_xor_sync(0xffffffffu, t, 16);
    float p = __expf(t);

    float o = (acc + p * xl) / (z + p) + __ldg(&b[lane]);
    if (do_relu) g_h[i] = fmaxf(o, 0.f);
    else         out[i] = o;
    g_acc[i] = 0.0f;                      // restore zero invariant (same thread)

    if (!do_relu) {                       // layer 2: restore node-state zeros
        __syncwarp();                     // all lanes done reading z/cnt/suma
        if (lane == 0) {
            g_z1[n] = 0.0f; g_z2[n] = 0.0f;
            g_cnt[n] = 0.0f; g_suma[n] = 0.0f;
        }
    }
}

// ---------------- launch ----------------------------------------------------
extern "C" void kernel_launch(void* const* d_in, const int* in_sizes, int n_in,
                              void* d_out, int out_size) {
    const float* x    = (const float*)d_in[0];
    const int*   src  = (const int*)  d_in[1];
    const int*   dst  = (const int*)  d_in[2];
    const float* ea   = (const float*)d_in[3];
    const float* Wl1  = (const float*)d_in[4];
    const float* bl1  = (const float*)d_in[5];
    const float* Wr1  = (const float*)d_in[6];
    const float* br1  = (const float*)d_in[7];
    const float* We1  = (const float*)d_in[8];
    const float* att1 = (const float*)d_in[9];
    const float* b1   = (const float*)d_in[10];
    const float* Wl2  = (const float*)d_in[11];
    const float* bl2  = (const float*)d_in[12];
    const float* Wr2  = (const float*)d_in[13];
    const float* br2  = (const float*)d_in[14];
    const float* We2  = (const float*)d_in[15];
    const float* att2 = (const float*)d_in[16];
    const float* b2   = (const float*)d_in[17];
    float* out = (float*)d_out;

    const int TB   = 256;
    const int NB32 = (N_NODES * FDIM + TB - 1) / TB;
    const int XB   = ((long)EHALF * 8 + TB - 1) / TB;   // 2 edges per octet
    const int GB   = (N_NODES + 63) / 64;

    // ---- layer 1 (edge pass also builds degree stats) ----
    k_gemm<128><<<GB, TB>>>((const float4*)x, Wl1, bl1, Wr1, br1);
    k_edge<<<XB, TB>>>(src, dst, ea, We1, att1, 0, 1);
    k_fin<<<NB32, TB>>>(We1, att1, b1, out, 0, 1);

    // ---- layer 2 ----
    k_gemm<32><<<GB, TB>>>(nullptr, Wl2, bl2, Wr2, br2);
    k_edge<<<XB, TB>>>(src, dst, ea, We2, att2, 1, 0);
    k_fin<<<NB32, TB>>>(We2, att2, b2, out, 1, 0);
}